// round 16
// baseline (speedup 1.0000x reference)
#include <cuda_runtime.h>
#include <cstddef>
#include <cstdint>

// Problem constants (fixed by setup_inputs)
#define RB   12
#define LB   32
#define MB   16
#define HHB  32
#define HFB  64
#define EB   132
#define BTOT 64
#define NB_PER 8
#define NGROUP (BTOT/NB_PER)
#define NBLOCKS (NGROUP*RB)   // 96 blocks = 8 clusters of 12
#define NTHREADS 256          // 8 warps: 4 compute (2 batches each) + 4 epilogue

struct __align__(16) SmemLayout {
    unsigned long long mbar[4][2];   // per-TEAM mbarriers (count 22 = 11 peers x 2 batches)
    // weights, row-per-output, padded strides (conflict-free LDS.128)
    float mw2[176*36];     // [(slot*16+m)][k] stride 36
    float aw2[11*32*20];   // [slot*32+l][m] stride 20
    float mb [176];
    float gsw2[32*36];
    float gcw2[32*36];
    float gsb[32];
    float lw2[64*68];      // [o][i0..63] stride 68
    float lbS[64];
    float ow2[32*68];      // [l][hf]
    float obS[32];
    float wih2[96*36];
    float whh2[96*36];
    float bihS[96];
    float bhhS[96];
    // activations
    float zsD [2][NB_PER][RB][LB];   // DSMEM-exchanged z (double buffer)
    float meanF[3][NB_PER][192];     // per-step means (176 used), triple buffer
    float incD [3][NB_PER][LB];
    float zpub [3][NB_PER][LB];
    float hbufT[NB_PER][HFB];
    float hgS  [NB_PER][HHB];
    int   elist[12];
    int   slist[12];
};

__device__ __forceinline__ float fsig(float x) { return 1.0f / (1.0f + __expf(-x)); }

__device__ __forceinline__ uint32_t smem_u32(const void* p) {
    uint32_t a;
    asm("{ .reg .u64 t; cvta.to.shared.u64 t, %1; cvt.u32.u64 %0, t; }"
        : "=r"(a) : "l"(p));
    return a;
}
__device__ __forceinline__ uint32_t mapa_rank(uint32_t laddr, uint32_t rank) {
    uint32_t r;
    asm("mapa.shared::cluster.u32 %0, %1, %2;" : "=r"(r) : "r"(laddr), "r"(rank));
    return r;
}
__device__ __forceinline__ void st_remote_f32(uint32_t addr, float v) {
    asm volatile("st.shared::cluster.f32 [%0], %1;" :: "r"(addr), "f"(v) : "memory");
}
__device__ __forceinline__ void mbar_arrive_remote(uint32_t addr) {
    asm volatile("mbarrier.arrive.release.cluster.shared::cluster.b64 _, [%0];"
                 :: "r"(addr) : "memory");
}
__device__ __forceinline__ void mbar_init(uint32_t addr, uint32_t cnt) {
    asm volatile("mbarrier.init.shared.b64 [%0], %1;" :: "r"(addr), "r"(cnt) : "memory");
}
__device__ __forceinline__ void mbar_wait(uint32_t addr, uint32_t parity) {
    uint32_t done;
    do {
        asm volatile(
            "{\n\t.reg .pred p;\n\t"
            "mbarrier.try_wait.parity.acquire.cluster.shared::cta.b64 p, [%1], %2, 0x989680;\n\t"
            "selp.b32 %0, 1, 0, p;\n\t}"
            : "=r"(done) : "r"(addr), "r"(parity) : "memory");
    } while (!done);
}
__device__ __forceinline__ void cluster_sync_all() {
    asm volatile("barrier.cluster.arrive.aligned;" ::: "memory");
    asm volatile("barrier.cluster.wait.aligned;" ::: "memory");
}
__device__ __forceinline__ void bar_sync64(int id) {
    asm volatile("bar.sync %0, 64;" :: "r"(id) : "memory");
}
__device__ __forceinline__ void bar_arrive64(int id) {
    asm volatile("bar.arrive %0, 64;" :: "r"(id) : "memory");
}

// dual-batch dot-32: ONE weight stream, two activation streams (broadcast)
#define DOT32X2(aA0, aA1, aB0, aB1, WP, APA, APB)                     \
    {                                                                 \
        _Pragma("unroll")                                             \
        for (int _q = 0; _q < 8; _q++) {                              \
            float4 x = (WP)[_q];                                      \
            float4 vA = (APA)[_q], vB = (APB)[_q];                    \
            aA0 = fmaf(x.x, vA.x, aA0); aA1 = fmaf(x.y, vA.y, aA1);   \
            aA0 = fmaf(x.z, vA.z, aA0); aA1 = fmaf(x.w, vA.w, aA1);   \
            aB0 = fmaf(x.x, vB.x, aB0); aB1 = fmaf(x.y, vB.y, aB1);   \
            aB0 = fmaf(x.z, vB.z, aB0); aB1 = fmaf(x.w, vB.w, aB1);   \
        }                                                             \
    }

__global__ void __launch_bounds__(NTHREADS, 1) __cluster_dims__(RB, 1, 1)
nv_main_kernel(
    const float* __restrict__ z0,  const float* __restrict__ h0,
    const float* __restrict__ mean_w, const float* __restrict__ mean_b,
    const float* __restrict__ add_w,
    const float* __restrict__ gsw, const float* __restrict__ gsb_g,
    const float* __restrict__ gcw,
    const float* __restrict__ lw,  const float* __restrict__ lb_g,
    const float* __restrict__ ow,  const float* __restrict__ ob_g,
    const float* __restrict__ wih, const float* __restrict__ whh,
    const float* __restrict__ bih_g, const float* __restrict__ bhh_g,
    const int* __restrict__ src_idx, const int* __restrict__ tgt_idx,
    int T,
    float* __restrict__ zt, float* __restrict__ hf, float* __restrict__ ms)
{
    extern __shared__ char smraw[];
    SmemLayout& sm = *reinterpret_cast<SmemLayout*>(smraw);
    const int tid = threadIdx.x;
    const int g = blockIdx.x / RB;
    const int r = blockIdx.x % RB;
    const int b0 = g * NB_PER;

    // ---- incoming-edge list ----
    for (int e = tid; e < EB; e += NTHREADS) {
        if (tgt_idx[e] == r) {
            int s = src_idx[e];
            int slot = (s < r) ? s : s - 1;
            sm.elist[slot] = e;
            sm.slist[slot] = s;
        }
    }
    if (tid < 4*2) mbar_init(smem_u32(&sm.mbar[tid >> 1][tid & 1]), 22);
    __syncthreads();

    // ---- cache weights ----
    for (int idx = tid; idx < 176*32; idx += NTHREADS) {
        int row = idx >> 5, k = idx & 31;
        int slot = row >> 4, m = row & 15;
        sm.mw2[row*36 + k] = mean_w[((size_t)sm.elist[slot]*MB + m)*LB + k];
    }
    for (int idx = tid; idx < 11*32*16; idx += NTHREADS) {
        int row = idx >> 4, m = idx & 15;           // row = slot*32 + l
        int slot = row >> 5, l = row & 31;
        sm.aw2[row*20 + m] = add_w[((size_t)sm.elist[slot]*LB + l)*MB + m];
    }
    for (int idx = tid; idx < 176; idx += NTHREADS) {
        int slot = idx >> 4, m = idx & 15;
        sm.mb[idx] = mean_b[sm.elist[slot]*MB + m];
    }
    for (int idx = tid; idx < 32*32; idx += NTHREADS) {
        int o = idx >> 5, i = idx & 31;
        sm.gsw2[o*36 + i] = gsw[((size_t)r*LB + o)*LB + i];
        sm.gcw2[o*36 + i] = gcw[((size_t)r*LB + o)*LB + i];
    }
    if (tid < 32) sm.gsb[tid] = gsb_g[r*LB + tid];
    for (int idx = tid; idx < 64*64; idx += NTHREADS) {
        int o = idx >> 6, i = idx & 63;
        sm.lw2[o*68 + i] = lw[((size_t)r*HFB + o)*(2*LB) + i];
    }
    if (tid < 64) sm.lbS[tid] = lb_g[r*HFB + tid];
    for (int idx = tid; idx < 32*64; idx += NTHREADS) {
        int l = idx >> 6, i = idx & 63;
        sm.ow2[l*68 + i] = ow[((size_t)r*LB + l)*HFB + i];
    }
    if (tid < 32) sm.obS[tid] = ob_g[r*LB + tid];
    for (int idx = tid; idx < 96*32; idx += NTHREADS) {
        int j = idx >> 5, i = idx & 31;
        sm.wih2[j*36 + i] = wih[((size_t)r*96 + j)*LB + i];
        sm.whh2[j*36 + i] = whh[((size_t)r*96 + j)*HHB + i];
    }
    if (tid < 96) { sm.bihS[tid] = bih_g[r*96 + tid]; sm.bhhS[tid] = bhh_g[r*96 + tid]; }

    // ---- init state ----
    for (int idx = tid; idx < NB_PER*RB*LB; idx += NTHREADS) {
        int bb = idx / (RB*LB); int rem = idx % (RB*LB);
        int rr = rem >> 5, i = rem & 31;
        sm.zsD[0][bb][rr][i] = z0[((size_t)(b0+bb)*RB + rr)*LB + i];
    }
    for (int idx = tid; idx < NB_PER*HHB; idx += NTHREADS) {
        int bb = idx >> 5, j = idx & 31;
        sm.hgS[bb][j] = h0[((size_t)(b0+bb)*RB + r)*HHB + j];
    }
    __syncthreads();
    cluster_sync_all();

    const int w    = tid >> 5;          // 0..7
    const int lane = tid & 31;
    const int sub = lane >> 4, m16 = lane & 15;

    if (w < 4) {
        // ============ COMPUTE WARP c = w: batches pA=2c, pB=2c+1 ============
        const int c = w;
        const int pA = 2*c, pB = 2*c + 1;
        const int SIG = 1 + c, ACK = 5 + c, MEANS = 9 + c;

        const uint32_t smem_base = smem_u32(smraw);
        uint32_t pdelta[11];
        #pragma unroll
        for (int k = 0; k < 11; k++) {
            uint32_t prank = (uint32_t)(k + (k >= r ? 1 : 0));
            pdelta[k] = mapa_rank(smem_base, prank) - smem_base;
        }
        uint32_t laneDelta = 0u;
        #pragma unroll
        for (int k = 0; k < 11; k++)
            if (lane == k) laneDelta = pdelta[k];
        const uint32_t mbar_base = smem_u32(&sm.mbar[0][0]);
        const uint32_t mbar_c = mbar_base + (uint32_t)(c*16);   // this team's pair

        // fixed per-lane weight row pointers
        const float4* wp_gsw  = (const float4*)&sm.gsw2[lane*36];
        const float4* wp_gcw  = (const float4*)&sm.gcw2[lane*36];
        const float4* wp_lw0a = (const float4*)&sm.lw2[(lane     )*68];
        const float4* wp_lw1a = (const float4*)&sm.lw2[(lane + 32)*68];
        const float4* wp_lw0b = (const float4*)&sm.lw2[(lane     )*68 + 32];
        const float4* wp_lw1b = (const float4*)&sm.lw2[(lane + 32)*68 + 32];

        // ow weights: REGISTER-resident for the whole run
        float4 owr[16];
        {
            const float4* wp_ow = (const float4*)&sm.ow2[lane*68];
            #pragma unroll
            for (int q = 0; q < 16; q++) owr[q] = wp_ow[q];
        }

        // per-lane mean rows / sources — compute handles rounds 0..2 (slots 0..5)
        int mrow_[3], msrc_[3];
        #pragma unroll
        for (int rd = 0; rd < 3; rd++) {
            int slot = 2*rd + sub;
            mrow_[rd] = slot*16 + m16;
            msrc_[rd] = sm.slist[slot];
        }

        int buf3 = 0;
        for (int t = 0; t < T; t++) {
            if (t >= 2) bar_sync64(ACK);     // epi finished step t-2
            const int buf = t & 1;
            const float4* zroA = (const float4*)&sm.zsD[buf][pA][r][0];
            const float4* zroB = (const float4*)&sm.zsD[buf][pB][r][0];

            // ---- S0: own-state dots, dual-batch weight reuse ----
            float gsA, gsB, lz0A, lz0B, lz1A, lz1B;
            {
                float a0 = sm.gsb[lane], a1 = 0.f, b0v = sm.gsb[lane], b1 = 0.f;
                DOT32X2(a0, a1, b0v, b1, wp_gsw, zroA, zroB);
                gsA = a0 + a1; gsB = b0v + b1;
            }
            {
                float a0 = sm.lbS[lane], a1 = 0.f, b0v = sm.lbS[lane], b1 = 0.f;
                DOT32X2(a0, a1, b0v, b1, wp_lw0a, zroA, zroB);
                lz0A = a0 + a1; lz0B = b0v + b1;
            }
            {
                float a0 = sm.lbS[lane+32], a1 = 0.f, b0v = sm.lbS[lane+32], b1 = 0.f;
                DOT32X2(a0, a1, b0v, b1, wp_lw1a, zroA, zroB);
                lz1A = a0 + a1; lz1B = b0v + b1;
            }

            // ---- wait peers' z(t-1): ONE merged team barrier (count 22) ----
            if (t > 0)
                mbar_wait(mbar_c + (uint32_t)(((t - 1) & 1) * 8),
                          (uint32_t)(((t - 1) >> 1) & 1));

            // ---- S1a (half): mean slots 0..5, dual batch ----
            {
                float* mA = &sm.meanF[buf3][pA][0];
                float* mB = &sm.meanF[buf3][pB][0];
                #pragma unroll
                for (int rd = 0; rd < 3; rd++) {
                    const float4* wp = (const float4*)&sm.mw2[mrow_[rd]*36];
                    const float4* apA = (const float4*)&sm.zsD[buf][pA][msrc_[rd]][0];
                    const float4* apB = (const float4*)&sm.zsD[buf][pB][msrc_[rd]][0];
                    float a0 = sm.mb[mrow_[rd]], a1 = 0.f, b0v = sm.mb[mrow_[rd]], b1 = 0.f;
                    DOT32X2(a0, a1, b0v, b1, wp, apA, apB);
                    mA[mrow_[rd]] = a0 + a1;
                    mB[mrow_[rd]] = b0v + b1;
                }
            }
            bar_sync64(MEANS);   // epi wrote slots 6..10; our slots 0..5 visible warp-wide

            // ---- S1b: projection, 11 slots x 2 batches ----
            {
                const float4* mpA = (const float4*)&sm.meanF[buf3][pA][0];
                const float4* mpB = (const float4*)&sm.meanF[buf3][pB][0];
                float a0=0.f,a1=0.f,a2=0.f,a3=0.f;
                float b0v=0.f,b1=0.f,b2=0.f,b3=0.f;
                #pragma unroll
                for (int sl = 0; sl < 11; sl++) {
                    const float4* wpj = (const float4*)&sm.aw2[(sl*32 + lane)*20];
                    #pragma unroll
                    for (int q = 0; q < 4; q++) {
                        float4 x = wpj[q];
                        float4 vA = mpA[sl*4 + q], vB = mpB[sl*4 + q];
                        a0  = fmaf(x.x, vA.x, a0 ); a1 = fmaf(x.y, vA.y, a1);
                        a2  = fmaf(x.z, vA.z, a2 ); a3 = fmaf(x.w, vA.w, a3);
                        b0v = fmaf(x.x, vB.x, b0v); b1 = fmaf(x.y, vB.y, b1);
                        b2  = fmaf(x.z, vB.z, b2 ); b3 = fmaf(x.w, vB.w, b3);
                    }
                }
                sm.incD[buf3][pA][lane] = (a0 + a1) + (a2 + a3);
                sm.incD[buf3][pB][lane] = (b0v + b1) + (b2 + b3);
            }
            __syncwarp();

            // ---- S2: gate + hidden inc-half, dual batch ----
            const float4* iaA = (const float4*)&sm.incD[buf3][pA][0];
            const float4* iaB = (const float4*)&sm.incD[buf3][pB][0];
            float gateA, gateB;
            {
                float a0 = gsA, a1 = 0.f, b0v = gsB, b1 = 0.f;
                DOT32X2(a0, a1, b0v, b1, wp_gcw, iaA, iaB);
                gateA = fsig(a0 + a1); gateB = fsig(b0v + b1);
            }
            {
                float a0 = lz0A, a1 = 0.f, b0v = lz0B, b1 = 0.f;
                DOT32X2(a0, a1, b0v, b1, wp_lw0b, iaA, iaB);
                const float vA = a0 + a1, vB = b0v + b1;
                sm.hbufT[pA][lane] = vA * fsig(vA);
                sm.hbufT[pB][lane] = vB * fsig(vB);
            }
            {
                float a0 = lz1A, a1 = 0.f, b0v = lz1B, b1 = 0.f;
                DOT32X2(a0, a1, b0v, b1, wp_lw1b, iaA, iaB);
                const float vA = a0 + a1, vB = b0v + b1;
                sm.hbufT[pA][lane + 32] = vA * fsig(vA);
                sm.hbufT[pB][lane + 32] = vB * fsig(vB);
            }
            __syncwarp();

            // ---- S3: out layer (registers) + z update + publish ----
            {
                const float4* apA = (const float4*)&sm.hbufT[pA][0];
                const float4* apB = (const float4*)&sm.hbufT[pB][0];
                float a0 = sm.obS[lane], a1 = 0.f, a2 = 0.f, a3 = 0.f;
                float b0v = sm.obS[lane], b1 = 0.f, b2 = 0.f, b3 = 0.f;
                #pragma unroll
                for (int q = 0; q < 16; q++) {
                    float4 x = owr[q];
                    float4 vA = apA[q], vB = apB[q];
                    a0  = fmaf(x.x, vA.x, a0 ); a1 = fmaf(x.y, vA.y, a1);
                    a2  = fmaf(x.z, vA.z, a2 ); a3 = fmaf(x.w, vA.w, a3);
                    b0v = fmaf(x.x, vB.x, b0v); b1 = fmaf(x.y, vB.y, b1);
                    b2  = fmaf(x.z, vB.z, b2 ); b3 = fmaf(x.w, vB.w, b3);
                }
                const float tgA = tanhf((a0 + a1) + (a2 + a3));
                const float tgB = tanhf((b0v + b1) + (b2 + b3));
                const float zoA = sm.zsD[buf][pA][r][lane];
                const float zoB = sm.zsD[buf][pB][r][lane];
                const float znA = fmaf(0.1f * gateA, tgA - zoA, zoA);
                const float znB = fmaf(0.1f * gateB, tgB - zoB, zoB);

                const int nxt = buf ^ 1;
                sm.zsD[nxt][pA][r][lane] = znA;
                sm.zsD[nxt][pB][r][lane] = znB;
                sm.zpub[buf3][pA][lane]  = znA;
                sm.zpub[buf3][pB][lane]  = znB;
                const uint32_t zaddrA = smem_base +
                    (uint32_t)((const char*)&sm.zsD[nxt][pA][r][lane] - (const char*)&sm);
                const uint32_t zaddrB = smem_base +
                    (uint32_t)((const char*)&sm.zsD[nxt][pB][r][lane] - (const char*)&sm);
                #pragma unroll
                for (int k = 0; k < 11; k++) {
                    st_remote_f32(zaddrA + pdelta[k], znA);
                    st_remote_f32(zaddrB + pdelta[k], znB);
                }
                __syncwarp();
                if (lane < 11) {
                    const uint32_t off = (uint32_t)((t & 1) * 8);
                    mbar_arrive_remote(mbar_c + off + laneDelta);  // batch A arrive
                    mbar_arrive_remote(mbar_c + off + laneDelta);  // batch B arrive
                }
            }
            bar_arrive64(SIG);               // step-t data ready for epilogue

            buf3 = (buf3 == 2) ? 0 : buf3 + 1;
        }
    } else {
        // ============ EPILOGUE WARP e = w-4: batches pA=2e, pB=2e+1 ============
        const int e = w - 4;
        const int pA = 2*e, pB = 2*e + 1;
        const int SIG = 1 + e, ACK = 5 + e, MEANS = 9 + e;
        float hnewA = 0.0f, hnewB = 0.0f;

        const uint32_t mbar_base = smem_u32(&sm.mbar[0][0]);
        const uint32_t mbar_c = mbar_base + (uint32_t)(e*16);

        const float4* w0h = (const float4*)&sm.whh2[(lane   )*36];
        const float4* w1h = (const float4*)&sm.whh2[(lane+32)*36];
        const float4* w2h = (const float4*)&sm.whh2[(lane+64)*36];
        const float4* w0i = (const float4*)&sm.wih2[(lane   )*36];
        const float4* w1i = (const float4*)&sm.wih2[(lane+32)*36];
        const float4* w2i = (const float4*)&sm.wih2[(lane+64)*36];

        // epi handles mean rounds 3..5 (slots 6..10; slot 11 invalid for sub=1)
        int mrow_[3], msrc_[3];
        #pragma unroll
        for (int rd = 0; rd < 3; rd++) {
            int slot = 6 + 2*rd + sub;
            int slc = (slot < 11) ? slot : 10;
            mrow_[rd] = slc*16 + m16;
            msrc_[rd] = sm.slist[slc];
        }

        int buf3 = 0;
        for (int t = 0; t < T; t++) {
            const int buf = t & 1;
            // whh dots on own h (before mbar wait — h is epi-local)
            float ghA0, ghA1, ghA2, ghB0, ghB1, ghB2;
            {
                const float4* hpA = (const float4*)&sm.hgS[pA][0];
                const float4* hpB = (const float4*)&sm.hgS[pB][0];
                float a0 = sm.bhhS[lane],  a1 = 0.f, b0v = sm.bhhS[lane],  b1 = 0.f;
                DOT32X2(a0, a1, b0v, b1, w0h, hpA, hpB);
                ghA0 = a0 + a1; ghB0 = b0v + b1;
                float c0 = sm.bhhS[lane+32], c1 = 0.f, d0 = sm.bhhS[lane+32], d1 = 0.f;
                DOT32X2(c0, c1, d0, d1, w1h, hpA, hpB);
                ghA1 = c0 + c1; ghB1 = d0 + d1;
                float e0 = sm.bhhS[lane+64], e1 = 0.f, f0 = sm.bhhS[lane+64], f1 = 0.f;
                DOT32X2(e0, e1, f0, f1, w2h, hpA, hpB);
                ghA2 = e0 + e1; ghB2 = f0 + f1;
            }

            // wait peers' z(t-1) (same team mbarrier; observing wait)
            if (t > 0)
                mbar_wait(mbar_c + (uint32_t)(((t - 1) & 1) * 8),
                          (uint32_t)(((t - 1) >> 1) & 1));

            // mean slots 6..10 (dual batch), then hand to compute
            {
                float* mA = &sm.meanF[buf3][pA][0];
                float* mB = &sm.meanF[buf3][pB][0];
                #pragma unroll
                for (int rd = 0; rd < 3; rd++) {
                    if (6 + 2*rd + sub < 11) {
                        const float4* wp = (const float4*)&sm.mw2[mrow_[rd]*36];
                        const float4* apA = (const float4*)&sm.zsD[buf][pA][msrc_[rd]][0];
                        const float4* apB = (const float4*)&sm.zsD[buf][pB][msrc_[rd]][0];
                        float a0 = sm.mb[mrow_[rd]], a1 = 0.f;
                        float b0v = sm.mb[mrow_[rd]], b1 = 0.f;
                        DOT32X2(a0, a1, b0v, b1, wp, apA, apB);
                        mA[mrow_[rd]] = a0 + a1;
                        mB[mrow_[rd]] = b0v + b1;
                    }
                }
            }
            bar_arrive64(MEANS);             // compute may proceed to S1b

            bar_sync64(SIG);                 // compute published step t

            // wih dots + GRU, dual batch
            {
                const float4* ipA = (const float4*)&sm.incD[buf3][pA][0];
                const float4* ipB = (const float4*)&sm.incD[buf3][pB][0];
                float a0 = sm.bihS[lane],  a1 = 0.f, b0v = sm.bihS[lane],  b1 = 0.f;
                DOT32X2(a0, a1, b0v, b1, w0i, ipA, ipB);
                float c0 = sm.bihS[lane+32], c1 = 0.f, d0 = sm.bihS[lane+32], d1 = 0.f;
                DOT32X2(c0, c1, d0, d1, w1i, ipA, ipB);
                float e0 = sm.bihS[lane+64], e1 = 0.f, f0 = sm.bihS[lane+64], f1 = 0.f;
                DOT32X2(e0, e1, f0, f1, w2i, ipA, ipB);

                const float grA = fsig((a0 + a1) + ghA0);
                const float gzA = fsig((c0 + c1) + ghA1);
                const float nnA = tanhf(fmaf(grA, ghA2, e0 + e1));
                const float hoA = sm.hgS[pA][lane];
                hnewA = (1.0f - gzA)*nnA + gzA*hoA;
                sm.hgS[pA][lane] = hnewA;

                const float grB = fsig((b0v + b1) + ghB0);
                const float gzB = fsig((d0 + d1) + ghB1);
                const float nnB = tanhf(fmaf(grB, ghB2, f0 + f1));
                const float hoB = sm.hgS[pB][lane];
                hnewB = (1.0f - gzB)*nnB + gzB*hoB;
                sm.hgS[pB][lane] = hnewB;
            }
            __syncwarp();

            // global stores (zt, ms) for both batches
            zt[(((size_t)(b0 + pA)*T + t)*RB + r)*LB + lane] = sm.zpub[buf3][pA][lane];
            zt[(((size_t)(b0 + pB)*T + t)*RB + r)*LB + lane] = sm.zpub[buf3][pB][lane];
            {
                float* msA = ms + ((size_t)(b0 + pA)*T + t)*(EB*MB);
                float* msB = ms + ((size_t)(b0 + pB)*T + t)*(EB*MB);
                #pragma unroll
                for (int j = 0; j < 6; j++) {
                    const int idx = j*32 + lane;
                    if (idx < 176) {
                        const size_t off = (size_t)sm.elist[idx >> 4]*MB + (idx & 15);
                        msA[off] = sm.meanF[buf3][pA][idx];
                        msB[off] = sm.meanF[buf3][pB][idx];
                    }
                }
            }

            if (t < T - 2) bar_arrive64(ACK);
            buf3 = (buf3 == 2) ? 0 : buf3 + 1;
        }

        hf[((size_t)(b0 + pA)*RB + r)*HHB + lane] = hnewA;
        hf[((size_t)(b0 + pB)*RB + r)*HHB + lane] = hnewB;
    }

    cluster_sync_all();   // peers may still be writing our smem
}

extern "C" void kernel_launch(void* const* d_in, const int* in_sizes, int n_in,
                              void* d_out, int out_size) {
    const float* z0     = (const float*)d_in[0];
    const float* h0     = (const float*)d_in[1];
    const float* mean_w = (const float*)d_in[2];
    const float* mean_b = (const float*)d_in[3];
    const float* add_w  = (const float*)d_in[4];
    const float* gsw    = (const float*)d_in[5];
    const float* gsb    = (const float*)d_in[6];
    const float* gcw    = (const float*)d_in[7];
    const float* lw     = (const float*)d_in[8];
    const float* lb     = (const float*)d_in[9];
    const float* ow     = (const float*)d_in[10];
    const float* ob     = (const float*)d_in[11];
    const float* wih    = (const float*)d_in[12];
    const float* whh    = (const float*)d_in[13];
    const float* bih    = (const float*)d_in[14];
    const float* bhh    = (const float*)d_in[15];
    const int* src_idx  = (const int*)d_in[16];
    const int* tgt_idx  = (const int*)d_in[17];
    // out_size = B*T*R*L + B*R*Hh + B*T*E*M
    const int per_t = BTOT*RB*LB + BTOT*EB*MB;
    const int T = (out_size - BTOT*RB*HHB) / per_t;

    float* out = (float*)d_out;
    float* zt = out;
    float* hf = zt + (size_t)BTOT * T * RB * LB;
    float* ms = hf + (size_t)BTOT * RB * HHB;

    cudaFuncSetAttribute(nv_main_kernel,
                         cudaFuncAttributeMaxDynamicSharedMemorySize,
                         (int)sizeof(SmemLayout));
    cudaFuncSetAttribute(nv_main_kernel,
                         cudaFuncAttributeNonPortableClusterSizeAllowed, 1);

    nv_main_kernel<<<NBLOCKS, NTHREADS, sizeof(SmemLayout)>>>(
        z0, h0, mean_w, mean_b, add_w, gsw, gsb, gcw, lw, lb, ow, ob,
        wih, whh, bih, bhh, src_idx, tgt_idx, T, zt, hf, ms);
}

// round 17
// speedup vs baseline: 1.3683x; 1.3683x over previous
#include <cuda_runtime.h>
#include <cstddef>
#include <cstdint>

// Problem constants (fixed by setup_inputs)
#define RB   12
#define LB   32
#define MB   16
#define HHB  32
#define HFB  64
#define EB   132
#define BTOT 64
#define NB_PER 8
#define NGROUP (BTOT/NB_PER)
#define NBLOCKS (NGROUP*RB)   // 96 blocks = 8 clusters of 12
#define NTHREADS 256          // 8 warps: 4 compute (2 batches each) + 4 epilogue

struct __align__(16) SmemLayout {
    unsigned long long mbar[4][2];   // per-TEAM mbarriers (count 22 = 11 peers x 2 batches)
    // weights, row-per-output, padded strides (conflict-free LDS.128)
    float mw2[176*36];     // [(slot*16+m)][k] stride 36
    float aw2[11*32*20];   // [slot*32+l][m] stride 20
    float mb [176];
    float gsw2[32*36];
    float gcw2[32*36];
    float gsb[32];
    float lw2[64*68];      // [o][i0..63] stride 68
    float lbS[64];
    float ow2[32*68];      // [l][hf]
    float obS[32];
    float wih2[96*36];
    float whh2[96*36];
    float bihS[96];
    float bhhS[96];
    // activations
    float zsD [2][NB_PER][RB][LB];   // DSMEM-exchanged z (double buffer)
    float meanF[3][NB_PER][192];     // per-step means (176 used), triple buffer
    float incD [3][NB_PER][LB];
    float hbufT[NB_PER][HFB];
    float hgS  [NB_PER][HHB];
    int   elist[12];
    int   slist[12];
};

__device__ __forceinline__ float fsig(float x) { return 1.0f / (1.0f + __expf(-x)); }

__device__ __forceinline__ uint32_t smem_u32(const void* p) {
    uint32_t a;
    asm("{ .reg .u64 t; cvta.to.shared.u64 t, %1; cvt.u32.u64 %0, t; }"
        : "=r"(a) : "l"(p));
    return a;
}
__device__ __forceinline__ uint32_t mapa_rank(uint32_t laddr, uint32_t rank) {
    uint32_t r;
    asm("mapa.shared::cluster.u32 %0, %1, %2;" : "=r"(r) : "r"(laddr), "r"(rank));
    return r;
}
__device__ __forceinline__ void st_remote_f32(uint32_t addr, float v) {
    asm volatile("st.shared::cluster.f32 [%0], %1;" :: "r"(addr), "f"(v) : "memory");
}
__device__ __forceinline__ void mbar_arrive_remote2(uint32_t addr) {
    asm volatile("mbarrier.arrive.release.cluster.shared::cluster.b64 _, [%0], 2;"
                 :: "r"(addr) : "memory");
}
__device__ __forceinline__ void mbar_init(uint32_t addr, uint32_t cnt) {
    asm volatile("mbarrier.init.shared.b64 [%0], %1;" :: "r"(addr), "r"(cnt) : "memory");
}
__device__ __forceinline__ void mbar_wait(uint32_t addr, uint32_t parity) {
    uint32_t done;
    do {
        asm volatile(
            "{\n\t.reg .pred p;\n\t"
            "mbarrier.try_wait.parity.acquire.cluster.shared::cta.b64 p, [%1], %2, 0x989680;\n\t"
            "selp.b32 %0, 1, 0, p;\n\t}"
            : "=r"(done) : "r"(addr), "r"(parity) : "memory");
    } while (!done);
}
__device__ __forceinline__ void cluster_sync_all() {
    asm volatile("barrier.cluster.arrive.aligned;" ::: "memory");
    asm volatile("barrier.cluster.wait.aligned;" ::: "memory");
}
__device__ __forceinline__ void bar_sync64(int id) {
    asm volatile("bar.sync %0, 64;" :: "r"(id) : "memory");
}
__device__ __forceinline__ void bar_arrive64(int id) {
    asm volatile("bar.arrive %0, 64;" :: "r"(id) : "memory");
}

// dual-batch dot-32: ONE weight stream, two activation streams (broadcast)
#define DOT32X2(aA0, aA1, aB0, aB1, WP, APA, APB)                     \
    {                                                                 \
        _Pragma("unroll")                                             \
        for (int _q = 0; _q < 8; _q++) {                              \
            float4 x = (WP)[_q];                                      \
            float4 vA = (APA)[_q], vB = (APB)[_q];                    \
            aA0 = fmaf(x.x, vA.x, aA0); aA1 = fmaf(x.y, vA.y, aA1);   \
            aA0 = fmaf(x.z, vA.z, aA0); aA1 = fmaf(x.w, vA.w, aA1);   \
            aB0 = fmaf(x.x, vB.x, aB0); aB1 = fmaf(x.y, vB.y, aB1);   \
            aB0 = fmaf(x.z, vB.z, aB0); aB1 = fmaf(x.w, vB.w, aB1);   \
        }                                                             \
    }

__global__ void __launch_bounds__(NTHREADS, 1) __cluster_dims__(RB, 1, 1)
nv_main_kernel(
    const float* __restrict__ z0,  const float* __restrict__ h0,
    const float* __restrict__ mean_w, const float* __restrict__ mean_b,
    const float* __restrict__ add_w,
    const float* __restrict__ gsw, const float* __restrict__ gsb_g,
    const float* __restrict__ gcw,
    const float* __restrict__ lw,  const float* __restrict__ lb_g,
    const float* __restrict__ ow,  const float* __restrict__ ob_g,
    const float* __restrict__ wih, const float* __restrict__ whh,
    const float* __restrict__ bih_g, const float* __restrict__ bhh_g,
    const int* __restrict__ src_idx, const int* __restrict__ tgt_idx,
    int T,
    float* __restrict__ zt, float* __restrict__ hf, float* __restrict__ ms)
{
    extern __shared__ char smraw[];
    SmemLayout& sm = *reinterpret_cast<SmemLayout*>(smraw);
    const int tid = threadIdx.x;
    const int g = blockIdx.x / RB;
    const int r = blockIdx.x % RB;
    const int b0 = g * NB_PER;

    // ---- incoming-edge list ----
    for (int e = tid; e < EB; e += NTHREADS) {
        if (tgt_idx[e] == r) {
            int s = src_idx[e];
            int slot = (s < r) ? s : s - 1;
            sm.elist[slot] = e;
            sm.slist[slot] = s;
        }
    }
    if (tid < 4*2) mbar_init(smem_u32(&sm.mbar[tid >> 1][tid & 1]), 22);
    __syncthreads();

    // ---- cache weights ----
    for (int idx = tid; idx < 176*32; idx += NTHREADS) {
        int row = idx >> 5, k = idx & 31;
        int slot = row >> 4, m = row & 15;
        sm.mw2[row*36 + k] = mean_w[((size_t)sm.elist[slot]*MB + m)*LB + k];
    }
    for (int idx = tid; idx < 11*32*16; idx += NTHREADS) {
        int row = idx >> 4, m = idx & 15;           // row = slot*32 + l
        int slot = row >> 5, l = row & 31;
        sm.aw2[row*20 + m] = add_w[((size_t)sm.elist[slot]*LB + l)*MB + m];
    }
    for (int idx = tid; idx < 176; idx += NTHREADS) {
        int slot = idx >> 4, m = idx & 15;
        sm.mb[idx] = mean_b[sm.elist[slot]*MB + m];
    }
    for (int idx = tid; idx < 32*32; idx += NTHREADS) {
        int o = idx >> 5, i = idx & 31;
        sm.gsw2[o*36 + i] = gsw[((size_t)r*LB + o)*LB + i];
        sm.gcw2[o*36 + i] = gcw[((size_t)r*LB + o)*LB + i];
    }
    if (tid < 32) sm.gsb[tid] = gsb_g[r*LB + tid];
    for (int idx = tid; idx < 64*64; idx += NTHREADS) {
        int o = idx >> 6, i = idx & 63;
        sm.lw2[o*68 + i] = lw[((size_t)r*HFB + o)*(2*LB) + i];
    }
    if (tid < 64) sm.lbS[tid] = lb_g[r*HFB + tid];
    for (int idx = tid; idx < 32*64; idx += NTHREADS) {
        int l = idx >> 6, i = idx & 63;
        sm.ow2[l*68 + i] = ow[((size_t)r*LB + l)*HFB + i];
    }
    if (tid < 32) sm.obS[tid] = ob_g[r*LB + tid];
    for (int idx = tid; idx < 96*32; idx += NTHREADS) {
        int j = idx >> 5, i = idx & 31;
        sm.wih2[j*36 + i] = wih[((size_t)r*96 + j)*LB + i];
        sm.whh2[j*36 + i] = whh[((size_t)r*96 + j)*HHB + i];
    }
    if (tid < 96) { sm.bihS[tid] = bih_g[r*96 + tid]; sm.bhhS[tid] = bhh_g[r*96 + tid]; }

    // ---- init state ----
    for (int idx = tid; idx < NB_PER*RB*LB; idx += NTHREADS) {
        int bb = idx / (RB*LB); int rem = idx % (RB*LB);
        int rr = rem >> 5, i = rem & 31;
        sm.zsD[0][bb][rr][i] = z0[((size_t)(b0+bb)*RB + rr)*LB + i];
    }
    for (int idx = tid; idx < NB_PER*HHB; idx += NTHREADS) {
        int bb = idx >> 5, j = idx & 31;
        sm.hgS[bb][j] = h0[((size_t)(b0+bb)*RB + r)*HHB + j];
    }
    __syncthreads();
    cluster_sync_all();

    const int w    = tid >> 5;          // 0..7
    const int lane = tid & 31;

    if (w < 4) {
        // ============ COMPUTE WARP c = w: batches pA=2c, pB=2c+1 ============
        const int c = w;
        const int pA = 2*c, pB = 2*c + 1;
        const int SIG = 1 + c, ACK = 5 + c;
        const int sub = lane >> 4, m16 = lane & 15;

        const uint32_t smem_base = smem_u32(smraw);
        uint32_t pdelta[11];
        #pragma unroll
        for (int k = 0; k < 11; k++) {
            uint32_t prank = (uint32_t)(k + (k >= r ? 1 : 0));
            pdelta[k] = mapa_rank(smem_base, prank) - smem_base;
        }
        uint32_t laneDelta = 0u;
        #pragma unroll
        for (int k = 0; k < 11; k++)
            if (lane == k) laneDelta = pdelta[k];
        const uint32_t mbar_base = smem_u32(&sm.mbar[0][0]);
        const uint32_t mbar_c = mbar_base + (uint32_t)(c*16);   // this team's pair

        // fixed per-lane weight row pointers
        const float4* wp_gsw  = (const float4*)&sm.gsw2[lane*36];
        const float4* wp_gcw  = (const float4*)&sm.gcw2[lane*36];
        const float4* wp_lw0a = (const float4*)&sm.lw2[(lane     )*68];
        const float4* wp_lw1a = (const float4*)&sm.lw2[(lane + 32)*68];
        const float4* wp_lw0b = (const float4*)&sm.lw2[(lane     )*68 + 32];
        const float4* wp_lw1b = (const float4*)&sm.lw2[(lane + 32)*68 + 32];

        // ow weights: REGISTER-resident for the whole run
        float4 owr[16];
        {
            const float4* wp_ow = (const float4*)&sm.ow2[lane*68];
            #pragma unroll
            for (int q = 0; q < 16; q++) owr[q] = wp_ow[q];
        }

        // per-lane mean rows / sources (6 rounds; round 5 invalid for sub=1)
        int mrow_[6], msrc_[6];
        #pragma unroll
        for (int rd = 0; rd < 6; rd++) {
            int slot = 2*rd + sub;
            int slc = (slot < 11) ? slot : 10;
            mrow_[rd] = slc*16 + m16;
            msrc_[rd] = sm.slist[slc];
        }

        int buf3 = 0;
        for (int t = 0; t < T; t++) {
            if (t >= 2) bar_sync64(ACK);     // epi finished step t-2
            const int buf = t & 1;
            const float4* zroA = (const float4*)&sm.zsD[buf][pA][r][0];
            const float4* zroB = (const float4*)&sm.zsD[buf][pB][r][0];

            // ---- S0: own-state dots, dual-batch weight reuse ----
            float gsA, gsB, lz0A, lz0B, lz1A, lz1B;
            {
                float a0 = sm.gsb[lane], a1 = 0.f, b0v = sm.gsb[lane], b1 = 0.f;
                DOT32X2(a0, a1, b0v, b1, wp_gsw, zroA, zroB);
                gsA = a0 + a1; gsB = b0v + b1;
            }
            {
                float a0 = sm.lbS[lane], a1 = 0.f, b0v = sm.lbS[lane], b1 = 0.f;
                DOT32X2(a0, a1, b0v, b1, wp_lw0a, zroA, zroB);
                lz0A = a0 + a1; lz0B = b0v + b1;
            }
            {
                float a0 = sm.lbS[lane+32], a1 = 0.f, b0v = sm.lbS[lane+32], b1 = 0.f;
                DOT32X2(a0, a1, b0v, b1, wp_lw1a, zroA, zroB);
                lz1A = a0 + a1; lz1B = b0v + b1;
            }

            // ---- wait peers' z(t-1): ONE merged team barrier (count 22) ----
            if (t > 0)
                mbar_wait(mbar_c + (uint32_t)(((t - 1) & 1) * 8),
                          (uint32_t)(((t - 1) >> 1) & 1));

            // ---- S1a: 6 mean dots x 2 batches (weight reused) ----
            float mvA[6], mvB[6];
            #pragma unroll
            for (int rd = 0; rd < 6; rd++) {
                const float4* wp = (const float4*)&sm.mw2[mrow_[rd]*36];
                const float4* apA = (const float4*)&sm.zsD[buf][pA][msrc_[rd]][0];
                const float4* apB = (const float4*)&sm.zsD[buf][pB][msrc_[rd]][0];
                float a0 = sm.mb[mrow_[rd]], a1 = 0.f, b0v = sm.mb[mrow_[rd]], b1 = 0.f;
                DOT32X2(a0, a1, b0v, b1, wp, apA, apB);
                mvA[rd] = a0 + a1; mvB[rd] = b0v + b1;
            }
            {
                float* mA = &sm.meanF[buf3][pA][0];
                float* mB = &sm.meanF[buf3][pB][0];
                #pragma unroll
                for (int rd = 0; rd < 6; rd++)
                    if (2*rd + sub < 11) { mA[mrow_[rd]] = mvA[rd]; mB[mrow_[rd]] = mvB[rd]; }
            }
            __syncwarp();

            // ---- S1b: projection, 11 slots x 2 batches ----
            {
                const float4* mpA = (const float4*)&sm.meanF[buf3][pA][0];
                const float4* mpB = (const float4*)&sm.meanF[buf3][pB][0];
                float a0=0.f,a1=0.f,a2=0.f,a3=0.f;
                float b0v=0.f,b1=0.f,b2=0.f,b3=0.f;
                #pragma unroll
                for (int sl = 0; sl < 11; sl++) {
                    const float4* wpj = (const float4*)&sm.aw2[(sl*32 + lane)*20];
                    #pragma unroll
                    for (int q = 0; q < 4; q++) {
                        float4 x = wpj[q];
                        float4 vA = mpA[sl*4 + q], vB = mpB[sl*4 + q];
                        a0  = fmaf(x.x, vA.x, a0 ); a1 = fmaf(x.y, vA.y, a1);
                        a2  = fmaf(x.z, vA.z, a2 ); a3 = fmaf(x.w, vA.w, a3);
                        b0v = fmaf(x.x, vB.x, b0v); b1 = fmaf(x.y, vB.y, b1);
                        b2  = fmaf(x.z, vB.z, b2 ); b3 = fmaf(x.w, vB.w, b3);
                    }
                }
                sm.incD[buf3][pA][lane] = (a0 + a1) + (a2 + a3);
                sm.incD[buf3][pB][lane] = (b0v + b1) + (b2 + b3);
            }
            __syncwarp();

            // ---- S2: gate + hidden inc-half, dual batch ----
            const float4* iaA = (const float4*)&sm.incD[buf3][pA][0];
            const float4* iaB = (const float4*)&sm.incD[buf3][pB][0];
            float gateA, gateB;
            {
                float a0 = gsA, a1 = 0.f, b0v = gsB, b1 = 0.f;
                DOT32X2(a0, a1, b0v, b1, wp_gcw, iaA, iaB);
                gateA = fsig(a0 + a1); gateB = fsig(b0v + b1);
            }
            {
                float a0 = lz0A, a1 = 0.f, b0v = lz0B, b1 = 0.f;
                DOT32X2(a0, a1, b0v, b1, wp_lw0b, iaA, iaB);
                const float vA = a0 + a1, vB = b0v + b1;
                sm.hbufT[pA][lane] = vA * fsig(vA);
                sm.hbufT[pB][lane] = vB * fsig(vB);
            }
            {
                float a0 = lz1A, a1 = 0.f, b0v = lz1B, b1 = 0.f;
                DOT32X2(a0, a1, b0v, b1, wp_lw1b, iaA, iaB);
                const float vA = a0 + a1, vB = b0v + b1;
                sm.hbufT[pA][lane + 32] = vA * fsig(vA);
                sm.hbufT[pB][lane + 32] = vB * fsig(vB);
            }
            __syncwarp();

            // ---- S3: out layer (registers) + z update + publish ----
            {
                const float4* apA = (const float4*)&sm.hbufT[pA][0];
                const float4* apB = (const float4*)&sm.hbufT[pB][0];
                float a0 = sm.obS[lane], a1 = 0.f, a2 = 0.f, a3 = 0.f;
                float b0v = sm.obS[lane], b1 = 0.f, b2 = 0.f, b3 = 0.f;
                #pragma unroll
                for (int q = 0; q < 16; q++) {
                    float4 x = owr[q];
                    float4 vA = apA[q], vB = apB[q];
                    a0  = fmaf(x.x, vA.x, a0 ); a1 = fmaf(x.y, vA.y, a1);
                    a2  = fmaf(x.z, vA.z, a2 ); a3 = fmaf(x.w, vA.w, a3);
                    b0v = fmaf(x.x, vB.x, b0v); b1 = fmaf(x.y, vB.y, b1);
                    b2  = fmaf(x.z, vB.z, b2 ); b3 = fmaf(x.w, vB.w, b3);
                }
                const float tgA = tanhf((a0 + a1) + (a2 + a3));
                const float tgB = tanhf((b0v + b1) + (b2 + b3));
                const float zoA = sm.zsD[buf][pA][r][lane];
                const float zoB = sm.zsD[buf][pB][r][lane];
                const float znA = fmaf(0.1f * gateA, tgA - zoA, zoA);
                const float znB = fmaf(0.1f * gateB, tgB - zoB, zoB);

                const int nxt = buf ^ 1;
                sm.zsD[nxt][pA][r][lane] = znA;
                sm.zsD[nxt][pB][r][lane] = znB;
                const uint32_t zaddrA = smem_base +
                    (uint32_t)((const char*)&sm.zsD[nxt][pA][r][lane] - (const char*)&sm);
                const uint32_t zaddrB = smem_base +
                    (uint32_t)((const char*)&sm.zsD[nxt][pB][r][lane] - (const char*)&sm);
                #pragma unroll
                for (int k = 0; k < 11; k++) {
                    st_remote_f32(zaddrA + pdelta[k], znA);
                    st_remote_f32(zaddrB + pdelta[k], znB);
                }
                __syncwarp();
                if (lane < 11) {
                    const uint32_t off = (uint32_t)((t & 1) * 8);
                    mbar_arrive_remote2(mbar_c + off + laneDelta);  // count 2 = both batches
                }
            }
            bar_arrive64(SIG);               // step-t data ready for epilogue

            buf3 = (buf3 == 2) ? 0 : buf3 + 1;
        }
    } else {
        // ============ EPILOGUE WARP e = w-4: batches pA=2e, pB=2e+1 ============
        const int e = w - 4;
        const int pA = 2*e, pB = 2*e + 1;
        const int SIG = 1 + e, ACK = 5 + e;
        float hnewA = 0.0f, hnewB = 0.0f;

        const float4* w0h = (const float4*)&sm.whh2[(lane   )*36];
        const float4* w1h = (const float4*)&sm.whh2[(lane+32)*36];
        const float4* w2h = (const float4*)&sm.whh2[(lane+64)*36];
        const float4* w0i = (const float4*)&sm.wih2[(lane   )*36];
        const float4* w1i = (const float4*)&sm.wih2[(lane+32)*36];
        const float4* w2i = (const float4*)&sm.wih2[(lane+64)*36];

        int buf3 = 0;
        for (int t = 0; t < T; t++) {
            // whh dots on own h (before SIG), dual batch with weight reuse
            float ghA0, ghA1, ghA2, ghB0, ghB1, ghB2;
            {
                const float4* hpA = (const float4*)&sm.hgS[pA][0];
                const float4* hpB = (const float4*)&sm.hgS[pB][0];
                float a0 = sm.bhhS[lane],  a1 = 0.f, b0v = sm.bhhS[lane],  b1 = 0.f;
                DOT32X2(a0, a1, b0v, b1, w0h, hpA, hpB);
                ghA0 = a0 + a1; ghB0 = b0v + b1;
                float c0 = sm.bhhS[lane+32], c1 = 0.f, d0 = sm.bhhS[lane+32], d1 = 0.f;
                DOT32X2(c0, c1, d0, d1, w1h, hpA, hpB);
                ghA1 = c0 + c1; ghB1 = d0 + d1;
                float e0 = sm.bhhS[lane+64], e1 = 0.f, f0 = sm.bhhS[lane+64], f1 = 0.f;
                DOT32X2(e0, e1, f0, f1, w2h, hpA, hpB);
                ghA2 = e0 + e1; ghB2 = f0 + f1;
            }

            bar_sync64(SIG);                 // compute published step t

            // wih dots + GRU, dual batch
            {
                const float4* ipA = (const float4*)&sm.incD[buf3][pA][0];
                const float4* ipB = (const float4*)&sm.incD[buf3][pB][0];
                float a0 = sm.bihS[lane],  a1 = 0.f, b0v = sm.bihS[lane],  b1 = 0.f;
                DOT32X2(a0, a1, b0v, b1, w0i, ipA, ipB);
                float c0 = sm.bihS[lane+32], c1 = 0.f, d0 = sm.bihS[lane+32], d1 = 0.f;
                DOT32X2(c0, c1, d0, d1, w1i, ipA, ipB);
                float e0 = sm.bihS[lane+64], e1 = 0.f, f0 = sm.bihS[lane+64], f1 = 0.f;
                DOT32X2(e0, e1, f0, f1, w2i, ipA, ipB);

                const float grA = fsig((a0 + a1) + ghA0);
                const float gzA = fsig((c0 + c1) + ghA1);
                const float nnA = tanhf(fmaf(grA, ghA2, e0 + e1));
                const float hoA = sm.hgS[pA][lane];
                hnewA = (1.0f - gzA)*nnA + gzA*hoA;
                sm.hgS[pA][lane] = hnewA;

                const float grB = fsig((b0v + b1) + ghB0);
                const float gzB = fsig((d0 + d1) + ghB1);
                const float nnB = tanhf(fmaf(grB, ghB2, f0 + f1));
                const float hoB = sm.hgS[pB][lane];
                hnewB = (1.0f - gzB)*nnB + gzB*hoB;
                sm.hgS[pB][lane] = hnewB;
            }
            __syncwarp();

            // global stores (zt from zsD[nxt] local copy, ms from meanF)
            {
                const int nxt = (t & 1) ^ 1;
                zt[(((size_t)(b0 + pA)*T + t)*RB + r)*LB + lane] = sm.zsD[nxt][pA][r][lane];
                zt[(((size_t)(b0 + pB)*T + t)*RB + r)*LB + lane] = sm.zsD[nxt][pB][r][lane];
            }
            {
                float* msA = ms + ((size_t)(b0 + pA)*T + t)*(EB*MB);
                float* msB = ms + ((size_t)(b0 + pB)*T + t)*(EB*MB);
                #pragma unroll
                for (int j = 0; j < 6; j++) {
                    const int idx = j*32 + lane;
                    if (idx < 176) {
                        const size_t off = (size_t)sm.elist[idx >> 4]*MB + (idx & 15);
                        msA[off] = sm.meanF[buf3][pA][idx];
                        msB[off] = sm.meanF[buf3][pB][idx];
                    }
                }
            }

            if (t < T - 2) bar_arrive64(ACK);
            buf3 = (buf3 == 2) ? 0 : buf3 + 1;
        }

        hf[((size_t)(b0 + pA)*RB + r)*HHB + lane] = hnewA;
        hf[((size_t)(b0 + pB)*RB + r)*HHB + lane] = hnewB;
    }

    cluster_sync_all();   // peers may still be writing our smem
}

extern "C" void kernel_launch(void* const* d_in, const int* in_sizes, int n_in,
                              void* d_out, int out_size) {
    const float* z0     = (const float*)d_in[0];
    const float* h0     = (const float*)d_in[1];
    const float* mean_w = (const float*)d_in[2];
    const float* mean_b = (const float*)d_in[3];
    const float* add_w  = (const float*)d_in[4];
    const float* gsw    = (const float*)d_in[5];
    const float* gsb    = (const float*)d_in[6];
    const float* gcw    = (const float*)d_in[7];
    const float* lw     = (const float*)d_in[8];
    const float* lb     = (const float*)d_in[9];
    const float* ow     = (const float*)d_in[10];
    const float* ob     = (const float*)d_in[11];
    const float* wih    = (const float*)d_in[12];
    const float* whh    = (const float*)d_in[13];
    const float* bih    = (const float*)d_in[14];
    const float* bhh    = (const float*)d_in[15];
    const int* src_idx  = (const int*)d_in[16];
    const int* tgt_idx  = (const int*)d_in[17];
    // out_size = B*T*R*L + B*R*Hh + B*T*E*M
    const int per_t = BTOT*RB*LB + BTOT*EB*MB;
    const int T = (out_size - BTOT*RB*HHB) / per_t;

    float* out = (float*)d_out;
    float* zt = out;
    float* hf = zt + (size_t)BTOT * T * RB * LB;
    float* ms = hf + (size_t)BTOT * RB * HHB;

    cudaFuncSetAttribute(nv_main_kernel,
                         cudaFuncAttributeMaxDynamicSharedMemorySize,
                         (int)sizeof(SmemLayout));
    cudaFuncSetAttribute(nv_main_kernel,
                         cudaFuncAttributeNonPortableClusterSizeAllowed, 1);

    nv_main_kernel<<<NBLOCKS, NTHREADS, sizeof(SmemLayout)>>>(
        z0, h0, mean_w, mean_b, add_w, gsw, gsb, gcw, lw, lb, ow, ob,
        wih, whh, bih, bhh, src_idx, tgt_idx, T, zt, hf, ms);
}